// round 1
// baseline (speedup 1.0000x reference)
#include <cuda_runtime.h>

// ---------------------------------------------------------------------------
// 256-bin histogram of 33.5M fp32 values in [0,255], plus count = bs*hist[0].
//
// Strategy: privatized per-thread uint16 counter columns in shared memory
// (no atomics in the hot loop), conflict-free bank layout, float4 streaming
// loads with unroll-8 for MLP. 128 thr/block, 64.25KB smem -> 3 blocks/SM.
// ---------------------------------------------------------------------------

#define TPB        128
#define SBINS      257                      // 256 real bins + spill slot for b==256
#define WPB        64                       // 32-bit words per bin (128 uint16 cols)
#define SMEM_WORDS (SBINS * WPB)            // 16448 words
#define SMEM_BYTES (SMEM_WORDS * 4)         // 65792 bytes
#define NBLOCKS    456                      // 152 SMs * 3 blocks

__device__ unsigned int g_hist[256];

__global__ void zero_kernel() {
    g_hist[threadIdx.x] = 0u;
}

// ACC: bin = floor(x * 256/255); counter halfword index = b*128 + lanoff.
// Guard keeps any pathological value (<0 or >255+) from corrupting smem,
// and matches the reference's "drop out-of-range" semantics.
#define ACC(xv) do {                                                    \
    float _x = (xv);                                                    \
    int _b = (int)(_x * 1.00392156862745f); /* 256/255 */               \
    if ((unsigned)_b < (unsigned)SBINS)                                 \
        sh16[_b * 128 + lanoff] = (unsigned short)(sh16[_b * 128 + lanoff] + 1); \
} while (0)

__global__ void __launch_bounds__(TPB, 3)
hist_kernel(const float* __restrict__ inf, int n) {
    extern __shared__ unsigned int sh[];
    const int t = threadIdx.x;

    // zero private counters
    #pragma unroll 4
    for (int i = t; i < SMEM_WORDS; i += TPB) sh[i] = 0u;
    __syncthreads();

    // uint16 view. Counter for (bin, thread t):
    //   word  = bin*64 + (t & 63)   -> bank = (t & 63) % 32, conflict-free per warp
    //   half  = t >> 6              -> threads t, t+64 share a word, distinct bytes
    unsigned short* sh16 = (unsigned short*)sh;
    const int lanoff = ((t & 63) << 1) | (t >> 6);

    const int n4 = n >> 2;
    const float4* __restrict__ in4 = (const float4*)inf;
    const int stride = gridDim.x * TPB;
    int i = blockIdx.x * TPB + t;

    // main loop: 8 float4 loads batched up front (MLP), then 32 accumulates
    for (; i + 7 * stride < n4; i += 8 * stride) {
        float4 v0 = in4[i];
        float4 v1 = in4[i + stride];
        float4 v2 = in4[i + 2 * stride];
        float4 v3 = in4[i + 3 * stride];
        float4 v4 = in4[i + 4 * stride];
        float4 v5 = in4[i + 5 * stride];
        float4 v6 = in4[i + 6 * stride];
        float4 v7 = in4[i + 7 * stride];
        ACC(v0.x); ACC(v0.y); ACC(v0.z); ACC(v0.w);
        ACC(v1.x); ACC(v1.y); ACC(v1.z); ACC(v1.w);
        ACC(v2.x); ACC(v2.y); ACC(v2.z); ACC(v2.w);
        ACC(v3.x); ACC(v3.y); ACC(v3.z); ACC(v3.w);
        ACC(v4.x); ACC(v4.y); ACC(v4.z); ACC(v4.w);
        ACC(v5.x); ACC(v5.y); ACC(v5.z); ACC(v5.w);
        ACC(v6.x); ACC(v6.y); ACC(v6.z); ACC(v6.w);
        ACC(v7.x); ACC(v7.y); ACC(v7.z); ACC(v7.w);
    }
    for (; i < n4; i += stride) {
        float4 v = in4[i];
        ACC(v.x); ACC(v.y); ACC(v.z); ACC(v.w);
    }
    // scalar tail (n % 4 elements), handled by block 0
    if (blockIdx.x == 0 && t < (n & 3)) {
        ACC(inf[(n4 << 2) + t]);
    }
    __syncthreads();

    // Block reduction: thread t sums bins t and t+128 across 128 columns.
    // Rotation (k + t) keeps the 64-word sweep conflict-free.
    for (int b = t; b < 256; b += TPB) {
        unsigned int s = 0;
        #pragma unroll 8
        for (int k = 0; k < WPB; k++) {
            unsigned int w = sh[b * WPB + ((k + t) & (WPB - 1))];
            s += (w & 0xFFFFu) + (w >> 16);
        }
        atomicAdd(&g_hist[b], s);
    }
}

__global__ void finalize_kernel(const int* __restrict__ bsz, float* __restrict__ out) {
    int t = threadIdx.x;                 // 256 threads
    float h = (float)g_hist[t];
    out[t] = h;                          // hist[256]
    float h0 = (float)g_hist[0];         // broadcast read
    out[256 + t] = (float)(*bsz) * h0;   // count[256] = batchsize * hist[0]
}

extern "C" void kernel_launch(void* const* d_in, const int* in_sizes, int n_in,
                              void* d_out, int out_size) {
    // metadata order: [batchsize (1 elem int32), input (33.5M fp32)].
    // Pick by size to be robust.
    const float* x;
    const int*   bs;
    int n;
    if (n_in >= 2 && in_sizes[0] >= in_sizes[1]) {
        x = (const float*)d_in[0]; bs = (const int*)d_in[1]; n = in_sizes[0];
    } else {
        x = (const float*)d_in[1]; bs = (const int*)d_in[0]; n = in_sizes[1];
    }

    cudaFuncSetAttribute(hist_kernel,
                         cudaFuncAttributeMaxDynamicSharedMemorySize, SMEM_BYTES);

    zero_kernel<<<1, 256>>>();
    hist_kernel<<<NBLOCKS, TPB, SMEM_BYTES>>>(x, n);
    finalize_kernel<<<1, 256>>>(bs, (float*)d_out);
}

// round 2
// speedup vs baseline: 1.0671x; 1.0671x over previous
#include <cuda_runtime.h>

// ---------------------------------------------------------------------------
// 256-bin histogram of 33.5M fp32 in [0,255] + count = batchsize*hist[0].
//
// R2: uint8 per-thread-column counters (4 threads/word via byte lanes),
// 32.9KB static smem -> 6 blocks/SM = 24 warps/SM (2x R1). Per-block
// non-atomic partials replace zero_kernel + global atomics. Max 216
// elements/thread < 255 so byte counters never overflow (no flush).
// ---------------------------------------------------------------------------

#define TPB        128
#define SBINS      257                      // 256 bins + spill slot for b==256
#define WPB        32                       // 32-bit words per bin (128 u8 cols)
#define SMEM_WORDS (SBINS * WPB)            // 8224 words = 32896 bytes
#define NBLK       1216                     // 152 SMs * 8 (2 waves of 6-occ)

__device__ unsigned int g_part[NBLK * 256]; // per-block partial histograms

// bin = floor(x * 256/255); byte index = b*128 + lanoff (conflict-free).
#define ACC(xv) do {                                                    \
    float _x = (xv);                                                    \
    int _b = (int)(_x * 1.00392156862745f); /* 256/255 */               \
    if ((unsigned)_b < (unsigned)SBINS)                                 \
        sh8[_b * 128 + lanoff] = (unsigned char)(sh8[_b * 128 + lanoff] + 1); \
} while (0)

__global__ void __launch_bounds__(TPB, 6)
hist_kernel(const float* __restrict__ inf, int n) {
    __shared__ unsigned int sh[SMEM_WORDS];
    const int t = threadIdx.x;

    #pragma unroll 4
    for (int i = t; i < SMEM_WORDS; i += TPB) sh[i] = 0u;
    __syncthreads();

    // u8 view: counter(bin, t) at word bin*32+(t&31), byte (t>>5).
    // bank = t&31 -> conflict-free per warp; distinct bytes across warps.
    unsigned char* sh8 = (unsigned char*)sh;
    const int lanoff = ((t & 31) << 2) | (t >> 5);

    const int n4 = n >> 2;
    const float4* __restrict__ in4 = (const float4*)inf;
    const int stride = gridDim.x * TPB;
    int i = blockIdx.x * TPB + t;

    for (; i + 7 * stride < n4; i += 8 * stride) {
        float4 v0 = in4[i];
        float4 v1 = in4[i + stride];
        float4 v2 = in4[i + 2 * stride];
        float4 v3 = in4[i + 3 * stride];
        float4 v4 = in4[i + 4 * stride];
        float4 v5 = in4[i + 5 * stride];
        float4 v6 = in4[i + 6 * stride];
        float4 v7 = in4[i + 7 * stride];
        ACC(v0.x); ACC(v0.y); ACC(v0.z); ACC(v0.w);
        ACC(v1.x); ACC(v1.y); ACC(v1.z); ACC(v1.w);
        ACC(v2.x); ACC(v2.y); ACC(v2.z); ACC(v2.w);
        ACC(v3.x); ACC(v3.y); ACC(v3.z); ACC(v3.w);
        ACC(v4.x); ACC(v4.y); ACC(v4.z); ACC(v4.w);
        ACC(v5.x); ACC(v5.y); ACC(v5.z); ACC(v5.w);
        ACC(v6.x); ACC(v6.y); ACC(v6.z); ACC(v6.w);
        ACC(v7.x); ACC(v7.y); ACC(v7.z); ACC(v7.w);
    }
    for (; i < n4; i += stride) {
        float4 v = in4[i];
        ACC(v.x); ACC(v.y); ACC(v.z); ACC(v.w);
    }
    if (blockIdx.x == 0 && t < (n & 3)) {      // scalar tail
        ACC(inf[(n4 << 2) + t]);
    }
    __syncthreads();

    // Per-bin byte-sum via dp4a; write per-block partial (no atomics).
    for (int b = t; b < 256; b += TPB) {
        unsigned int s = 0;
        #pragma unroll 8
        for (int k = 0; k < WPB; k++) {
            unsigned int w = sh[b * WPB + ((k + t) & (WPB - 1))];
            s = __dp4a(w, 0x01010101u, s);
        }
        g_part[blockIdx.x * 256 + b] = s;
    }
}

// 257 blocks: blocks 0..255 reduce their bin; block 256 redundantly reduces
// bin 0 and writes count[0:256] = batchsize * hist[0].
__global__ void reduce_kernel(const int* __restrict__ bsz, float* __restrict__ out) {
    const int t = threadIdx.x;                       // 128 threads
    const int bin = (blockIdx.x == 256) ? 0 : blockIdx.x;

    unsigned int s = 0;
    for (int k = t; k < NBLK; k += TPB)
        s += g_part[k * 256 + bin];

    // warp reduce
    #pragma unroll
    for (int o = 16; o > 0; o >>= 1)
        s += __shfl_down_sync(0xFFFFFFFFu, s, o);

    __shared__ unsigned int wsum[4];
    if ((t & 31) == 0) wsum[t >> 5] = s;
    __syncthreads();
    __shared__ unsigned int total;
    if (t == 0) total = wsum[0] + wsum[1] + wsum[2] + wsum[3];
    __syncthreads();

    if (blockIdx.x < 256) {
        if (t == 0) out[blockIdx.x] = (float)total;
    } else {
        float c = (float)(*bsz) * (float)total;
        out[256 + t] = c;
        out[256 + t + 128] = c;
    }
}

extern "C" void kernel_launch(void* const* d_in, const int* in_sizes, int n_in,
                              void* d_out, int out_size) {
    const float* x;
    const int*   bs;
    int n;
    if (n_in >= 2 && in_sizes[0] >= in_sizes[1]) {
        x = (const float*)d_in[0]; bs = (const int*)d_in[1]; n = in_sizes[0];
    } else {
        x = (const float*)d_in[1]; bs = (const int*)d_in[0]; n = in_sizes[1];
    }

    hist_kernel<<<NBLK, TPB>>>(x, n);
    reduce_kernel<<<257, TPB>>>(bs, (float*)d_out);
}

// round 3
// speedup vs baseline: 1.2752x; 1.1950x over previous
#include <cuda_runtime.h>

// ---------------------------------------------------------------------------
// 256-bin histogram of 33.5M fp32 in [0,255] + count = batchsize*hist[0].
//
// R3: 4-way batched increments with collision correction breaks the
// LDS->IADD->STS serial chain (4 independent LDS in flight). uint8
// per-thread-column counters, conflict-free banks. Per-block global
// atomicAdd replaces the slow reduce kernel; finalize resets g_hist so
// every graph replay is idempotent (no zero kernel).
// ---------------------------------------------------------------------------

#define TPB        128
#define SBINS      257                      // 256 bins + spill slot for b==256
#define WPB        32                       // 32-bit words per bin (128 u8 cols)
#define SMEM_WORDS (SBINS * WPB)            // 8224 words = 32896 bytes
#define NBLK       1216                     // max 215 elems/thread < 255 (u8 ok)

__device__ unsigned int g_hist[256];        // zero-init at load; reset by finalize

#define BINC  1.00392156862745f             /* 256/255 */

__device__ __forceinline__ unsigned binof(float x) {
    unsigned b = (unsigned)(int)(x * BINC);
    return b > 256u ? 256u : b;             // IMNMX-style clamp into spill
}

// 4 elements of one lane: batched loads, collision-corrected adds, ordered stores.
#define ACC4(x0, x1, x2, x3) do {                                        \
    unsigned b0 = binof(x0), b1 = binof(x1), b2 = binof(x2), b3 = binof(x3); \
    unsigned a0 = b0 * 128 + lanoff, a1 = b1 * 128 + lanoff;             \
    unsigned a2 = b2 * 128 + lanoff, a3 = b3 * 128 + lanoff;             \
    unsigned c0 = sh8[a0], c1 = sh8[a1], c2 = sh8[a2], c3 = sh8[a3];     \
    c0 += 1u;                                                            \
    c1 += 1u + (b1 == b0);                                               \
    c2 += 1u + (b2 == b0) + (b2 == b1);                                  \
    c3 += 1u + (b3 == b0) + (b3 == b1) + (b3 == b2);                     \
    sh8[a0] = (unsigned char)c0;                                         \
    sh8[a1] = (unsigned char)c1;                                         \
    sh8[a2] = (unsigned char)c2;                                         \
    sh8[a3] = (unsigned char)c3;                                         \
} while (0)

__global__ void __launch_bounds__(TPB, 6)
hist_kernel(const float* __restrict__ inf, int n) {
    __shared__ unsigned int sh[SMEM_WORDS];
    const int t = threadIdx.x;

    #pragma unroll 4
    for (int i = t; i < SMEM_WORDS; i += TPB) sh[i] = 0u;
    __syncthreads();

    // u8 view: counter(bin, t) at byte bin*128 + (t&31)*4 + (t>>5).
    // bank = t&31 -> conflict-free per warp; distinct bytes across warps.
    unsigned char* sh8 = (unsigned char*)sh;
    const unsigned lanoff = ((t & 31) << 2) | (t >> 5);

    const int n4 = n >> 2;
    const float4* __restrict__ in4 = (const float4*)inf;
    const int stride = gridDim.x * TPB;
    int i = blockIdx.x * TPB + t;

    for (; i + 7 * stride < n4; i += 8 * stride) {
        float4 v0 = in4[i];
        float4 v1 = in4[i + stride];
        float4 v2 = in4[i + 2 * stride];
        float4 v3 = in4[i + 3 * stride];
        float4 v4 = in4[i + 4 * stride];
        float4 v5 = in4[i + 5 * stride];
        float4 v6 = in4[i + 6 * stride];
        float4 v7 = in4[i + 7 * stride];
        ACC4(v0.x, v0.y, v0.z, v0.w);
        ACC4(v1.x, v1.y, v1.z, v1.w);
        ACC4(v2.x, v2.y, v2.z, v2.w);
        ACC4(v3.x, v3.y, v3.z, v3.w);
        ACC4(v4.x, v4.y, v4.z, v4.w);
        ACC4(v5.x, v5.y, v5.z, v5.w);
        ACC4(v6.x, v6.y, v6.z, v6.w);
        ACC4(v7.x, v7.y, v7.z, v7.w);
    }
    for (; i < n4; i += stride) {
        float4 v = in4[i];
        ACC4(v.x, v.y, v.z, v.w);
    }
    if (blockIdx.x == 0 && t < (n & 3)) {      // scalar tail
        unsigned b = binof(inf[(n4 << 2) + t]);
        unsigned a = b * 128 + lanoff;
        sh8[a] = (unsigned char)(sh8[a] + 1);
    }
    __syncthreads();

    // Per-bin byte-sum via dp4a, then one global atomic per bin per block.
    for (int b = t; b < 256; b += TPB) {
        unsigned int s = 0;
        #pragma unroll 8
        for (int k = 0; k < WPB; k++)
            s = __dp4a(sh[b * WPB + ((k + t) & (WPB - 1))], 0x01010101u, s);
        atomicAdd(&g_hist[b], s);
    }
}

__global__ void finalize_kernel(const int* __restrict__ bsz, float* __restrict__ out) {
    const int t = threadIdx.x;               // 256 threads
    unsigned int h  = g_hist[t];
    unsigned int h0 = g_hist[0];
    __syncthreads();
    g_hist[t] = 0u;                          // reset for next graph replay
    out[t]       = (float)h;
    out[256 + t] = (float)(*bsz) * (float)h0;
}

extern "C" void kernel_launch(void* const* d_in, const int* in_sizes, int n_in,
                              void* d_out, int out_size) {
    const float* x;
    const int*   bs;
    int n;
    if (n_in >= 2 && in_sizes[0] >= in_sizes[1]) {
        x = (const float*)d_in[0]; bs = (const int*)d_in[1]; n = in_sizes[0];
    } else {
        x = (const float*)d_in[1]; bs = (const int*)d_in[0]; n = in_sizes[1];
    }

    hist_kernel<<<NBLK, TPB>>>(x, n);
    finalize_kernel<<<1, 256>>>(bs, (float*)d_out);
}